// round 10
// baseline (speedup 1.0000x reference)
#include <cuda_runtime.h>
#include <cstdint>

#define NN 20000
#define BB 64
#define EE 1280000
#define CAP 192                  // slab capacity per node (Poisson(64); 16 sigma)

// Scratch (allocation-free -> __device__ globals)
__device__ __align__(16) float g_xT[NN * BB];      // x transposed to [N, B]
__device__ int   g_cnt[NN];                        // zeroed by k_accum each launch
__device__ __align__(16) uint2 g_slab[NN * CAP];   // per-node records (src, coeff)

#define T_BLOCKS 1250   // transpose: 625 n-tiles x 2 b-halves
#define S_BLOCKS 1250   // scatter: 1250 x 256 threads x 4 edges = 1.28M

// ---------------------------------------------------------------------------
// K0: fused (independent) transpose + slab scatter.
//   blocks [0, T_BLOCKS)            : transpose x [B,N] -> xT [N,B]
//   blocks [T_BLOCKS, ...)          : scatter 4 edges/thread into slabs
// g_cnt is zero on entry (module init / k_accum of the previous launch).
// ---------------------------------------------------------------------------
__global__ void __launch_bounds__(256) k_front(const float* __restrict__ x,
                                               const float* __restrict__ adj,
                                               const float* __restrict__ w,
                                               const int* __restrict__ src,
                                               const int* __restrict__ dst) {
    if (blockIdx.x < T_BLOCKS) {
        // ---- transpose: 32n x 32b tile ----
        __shared__ float tile[32][33];   // tile[nn][bb], 33-pad: conflict-free
        const int n0 = (blockIdx.x >> 1) * 32;
        const int b0 = (blockIdx.x & 1) * 32;

        {
            // load: thread -> (bb = tid>>3, nv = (tid&7)*4), LDG.128 along n
            const int bb = threadIdx.x >> 3;
            const int nv = (threadIdx.x & 7) * 4;
            float4 v = *(const float4*)(x + (size_t)(b0 + bb) * NN + n0 + nv);
            tile[nv + 0][bb] = v.x;    // scalar STS, banks (nv+k+bb) distinct
            tile[nv + 1][bb] = v.y;
            tile[nv + 2][bb] = v.z;
            tile[nv + 3][bb] = v.w;
        }
        __syncthreads();
        {
            // store: thread -> (nl = tid>>3, bv = (tid&7)*4)
            // 4 scalar LDS (33-pad rows are NOT 16B aligned -> no LDS.128!),
            // banks (nl + bv + k) mod 32 distinct per k -> conflict-free.
            const int nl = threadIdx.x >> 3;
            const int bv = (threadIdx.x & 7) * 4;
            float4 v;
            v.x = tile[nl][bv + 0];
            v.y = tile[nl][bv + 1];
            v.z = tile[nl][bv + 2];
            v.w = tile[nl][bv + 3];
            *(float4*)(g_xT + (size_t)(n0 + nl) * 64 + b0 + bv) = v;  // STG.128
        }
    } else {
        // ---- scatter: 4 independent atomic+store chains per thread ----
        int t = (blockIdx.x - T_BLOCKS) * 256 + threadIdx.x;   // < 320000
        int4   s = __ldg(&((const int4*)src)[t]);
        int4   d = __ldg(&((const int4*)dst)[t]);
        float4 a = __ldg(&((const float4*)adj)[t]);
        float4 q = __ldg(&((const float4*)w)[t]);

        int p0 = atomicAdd(&g_cnt[d.x], 1);
        int p1 = atomicAdd(&g_cnt[d.y], 1);
        int p2 = atomicAdd(&g_cnt[d.z], 1);
        int p3 = atomicAdd(&g_cnt[d.w], 1);

        if (p0 < CAP) g_slab[(size_t)d.x * CAP + p0] =
            make_uint2((unsigned)s.x, __float_as_uint(a.x * q.x));
        if (p1 < CAP) g_slab[(size_t)d.y * CAP + p1] =
            make_uint2((unsigned)s.y, __float_as_uint(a.y * q.y));
        if (p2 < CAP) g_slab[(size_t)d.z * CAP + p2] =
            make_uint2((unsigned)s.z, __float_as_uint(a.z * q.z));
        if (p3 < CAP) g_slab[(size_t)d.w * CAP + p3] =
            make_uint2((unsigned)s.w, __float_as_uint(a.w * q.w));
    }
}

// ---------------------------------------------------------------------------
// K1: warp-per-node accumulation + fused epilogue (R8-proven inner loop +
// record prefetch). Resets g_cnt[n]=0 for the next launch.
// ---------------------------------------------------------------------------
__global__ void __launch_bounds__(256) k_accum(const float* __restrict__ x,
                                               const float* __restrict__ self_w,
                                               const float* __restrict__ bias,
                                               float* __restrict__ out) {
    __shared__ float sacc[8][65];
    const int wp = threadIdx.x >> 5;
    const int lane = threadIdx.x & 31;
    const int half = lane >> 4;
    const int q = lane & 15;
    const int n0 = blockIdx.x * 8;
    const int n = n0 + wp;

    const int cnt = min(g_cnt[n], CAP);
    if (lane == 0) g_cnt[n] = 0;           // ready for next launch
    int base = n * CAP;
    const int end = base + cnt;

    float4 acc = make_float4(0.f, 0.f, 0.f, 0.f);
    const int nfull = cnt >> 5;

    uint2 r_cur;
    if (nfull > 0) r_cur = g_slab[base + lane];
    for (int f = 0; f < nfull; f++, base += 32) {
        uint2 r_nxt;
        if (f + 1 < nfull) r_nxt = g_slab[base + 32 + lane];
        #pragma unroll
        for (int i = 0; i < 16; i++) {
            int idx = 2 * i + half;
            unsigned sv = __shfl_sync(0xffffffffu, r_cur.x, idx);
            float c = __uint_as_float(__shfl_sync(0xffffffffu, r_cur.y, idx));
            float4 v = *(const float4*)(g_xT + (size_t)sv * 64 + q * 4);
            acc.x = fmaf(c, v.x, acc.x);
            acc.y = fmaf(c, v.y, acc.y);
            acc.z = fmaf(c, v.z, acc.z);
            acc.w = fmaf(c, v.w, acc.w);
        }
        r_cur = r_nxt;
    }
    const int rem = end - base;
    if (rem > 0) {
        uint2 r = (lane < rem) ? g_slab[base + lane] : make_uint2(0u, 0u);
        const int npair = rem >> 1;
        for (int i = 0; i < npair; i++) {
            int idx = 2 * i + half;
            unsigned sv = __shfl_sync(0xffffffffu, r.x, idx);
            float c = __uint_as_float(__shfl_sync(0xffffffffu, r.y, idx));
            float4 v = *(const float4*)(g_xT + (size_t)sv * 64 + q * 4);
            acc.x = fmaf(c, v.x, acc.x);
            acc.y = fmaf(c, v.y, acc.y);
            acc.z = fmaf(c, v.z, acc.z);
            acc.w = fmaf(c, v.w, acc.w);
        }
        if (rem & 1) {
            unsigned sv = __shfl_sync(0xffffffffu, r.x, rem - 1);
            float c = __uint_as_float(__shfl_sync(0xffffffffu, r.y, rem - 1));
            c = (half == 0) ? c : 0.0f;
            float4 v = *(const float4*)(g_xT + (size_t)sv * 64 + q * 4);
            acc.x = fmaf(c, v.x, acc.x);
            acc.y = fmaf(c, v.y, acc.y);
            acc.z = fmaf(c, v.z, acc.z);
            acc.w = fmaf(c, v.w, acc.w);
        }
    }

    acc.x += __shfl_xor_sync(0xffffffffu, acc.x, 16);
    acc.y += __shfl_xor_sync(0xffffffffu, acc.y, 16);
    acc.z += __shfl_xor_sync(0xffffffffu, acc.z, 16);
    acc.w += __shfl_xor_sync(0xffffffffu, acc.w, 16);

    float sl = __ldg(&x[n]) * __ldg(&self_w[n]);  // x row 0
    float bs = __ldg(&bias[n]);
    if (half == 0) {
        sacc[wp][4 * q + 0] = fmaxf(fmaf(acc.x, sl, bs), 0.0f);
        sacc[wp][4 * q + 1] = fmaxf(fmaf(acc.y, sl, bs), 0.0f);
        sacc[wp][4 * q + 2] = fmaxf(fmaf(acc.z, sl, bs), 0.0f);
        sacc[wp][4 * q + 3] = fmaxf(fmaf(acc.w, sl, bs), 0.0f);
    }
    __syncthreads();

    #pragma unroll
    for (int e = threadIdx.x; e < 512; e += 256) {
        int b = e >> 3;
        int i = e & 7;
        out[(size_t)b * NN + n0 + i] = sacc[i][b];
    }
}

// ---------------------------------------------------------------------------
// Launch. Inputs: x, adj_values, w, self_w, b, src, dst.
// ---------------------------------------------------------------------------
extern "C" void kernel_launch(void* const* d_in, const int* in_sizes, int n_in,
                              void* d_out, int out_size) {
    const float* x      = (const float*)d_in[0];
    const float* adj    = (const float*)d_in[1];
    const float* w      = (const float*)d_in[2];
    const float* self_w = (const float*)d_in[3];
    const float* bias   = (const float*)d_in[4];
    const int*   src    = (const int*)d_in[5];
    const int*   dst    = (const int*)d_in[6];
    float* out = (float*)d_out;

    k_front<<<T_BLOCKS + S_BLOCKS, 256>>>(x, adj, w, src, dst);
    k_accum<<<NN / 8, 256>>>(x, self_w, bias, out);
}

// round 12
// speedup vs baseline: 1.3357x; 1.3357x over previous
#include <cuda_runtime.h>
#include <cstdint>

#define NN 20000
#define BB 64
#define EE 1280000
#define CAP 192                  // slab capacity per node (Poisson(64); 16 sigma)

// Scratch (allocation-free -> __device__ globals)
__device__ __align__(16) float g_xT[NN * BB];      // x transposed to [N, B]
__device__ int   g_cnt[NN];                        // zeroed in k_transpose
__device__ __align__(16) uint2 g_slab[NN * CAP];   // per-node records (src, coeff)

// ---------------------------------------------------------------------------
// K0: transpose x [B,N] -> xT [N,B]; zero g_cnt. Vectorized: LDG.128 in,
// conflict-free scalar LDS (33-pad rows are not 16B-aligned!), STG.128 out.
// 1250 blocks x 256 threads; one 32n x 32b tile per block.
// ---------------------------------------------------------------------------
__global__ void __launch_bounds__(256) k_transpose(const float* __restrict__ x) {
    __shared__ float tile[32][33];
    const int n0 = (blockIdx.x >> 1) * 32;   // 625 n-tiles
    const int b0 = (blockIdx.x & 1) * 32;

    // zero the counters (20000 ints over 1250 blocks)
    for (int i = blockIdx.x * 256 + threadIdx.x; i < NN; i += 1250 * 256)
        g_cnt[i] = 0;

    {
        // load: thread -> (bb = tid>>3, nv = (tid&7)*4), LDG.128 along n
        const int bb = threadIdx.x >> 3;
        const int nv = (threadIdx.x & 7) * 4;
        float4 v = *(const float4*)(x + (size_t)(b0 + bb) * NN + n0 + nv);
        tile[nv + 0][bb] = v.x;   // STS banks (nv+k+bb) distinct -> conflict-free
        tile[nv + 1][bb] = v.y;
        tile[nv + 2][bb] = v.z;
        tile[nv + 3][bb] = v.w;
    }
    __syncthreads();
    {
        // store: thread -> (nl = tid>>3, bv = (tid&7)*4); 4 scalar LDS,
        // banks (nl+bv+k) mod 32 distinct -> conflict-free; STG.128 out.
        const int nl = threadIdx.x >> 3;
        const int bv = (threadIdx.x & 7) * 4;
        float4 v;
        v.x = tile[nl][bv + 0];
        v.y = tile[nl][bv + 1];
        v.z = tile[nl][bv + 2];
        v.w = tile[nl][bv + 3];
        *(float4*)(g_xT + (size_t)(n0 + nl) * 64 + b0 + bv) = v;
    }
}

// ---------------------------------------------------------------------------
// K1: direct slab scatter (R8-proven). 4 edges/thread -> 4 independent
// atomic+store chains; vectorized edge-array loads.
// ---------------------------------------------------------------------------
__global__ void k_scatter(const float* __restrict__ adj,
                          const float* __restrict__ w,
                          const int* __restrict__ src,
                          const int* __restrict__ dst) {
    int t = blockIdx.x * 256 + threadIdx.x;      // < 320000 (EE/4)
    int4   s = __ldg(&((const int4*)src)[t]);
    int4   d = __ldg(&((const int4*)dst)[t]);
    float4 a = __ldg(&((const float4*)adj)[t]);
    float4 q = __ldg(&((const float4*)w)[t]);

    int p0 = atomicAdd(&g_cnt[d.x], 1);
    int p1 = atomicAdd(&g_cnt[d.y], 1);
    int p2 = atomicAdd(&g_cnt[d.z], 1);
    int p3 = atomicAdd(&g_cnt[d.w], 1);

    if (p0 < CAP) g_slab[(size_t)d.x * CAP + p0] =
        make_uint2((unsigned)s.x, __float_as_uint(a.x * q.x));
    if (p1 < CAP) g_slab[(size_t)d.y * CAP + p1] =
        make_uint2((unsigned)s.y, __float_as_uint(a.y * q.y));
    if (p2 < CAP) g_slab[(size_t)d.z * CAP + p2] =
        make_uint2((unsigned)s.z, __float_as_uint(a.z * q.z));
    if (p3 < CAP) g_slab[(size_t)d.w * CAP + p3] =
        make_uint2((unsigned)s.w, __float_as_uint(a.w * q.w));
}

// ---------------------------------------------------------------------------
// K2: warp-per-node accumulation + fused epilogue (R8-proven, NO prefetch —
// 32 regs / 86% occ shape). Half-warp h handles record 2i+h; lane q=lane&15
// owns features [4q,4q+4).
// ---------------------------------------------------------------------------
__global__ void __launch_bounds__(256) k_accum(const float* __restrict__ x,
                                               const float* __restrict__ self_w,
                                               const float* __restrict__ bias,
                                               float* __restrict__ out) {
    __shared__ float sacc[8][65];
    const int wp = threadIdx.x >> 5;
    const int lane = threadIdx.x & 31;
    const int half = lane >> 4;
    const int q = lane & 15;
    const int n0 = blockIdx.x * 8;
    const int n = n0 + wp;

    const int cnt = min(__ldg(&g_cnt[n]), CAP);
    int base = n * CAP;
    const int end = base + cnt;

    float4 acc = make_float4(0.f, 0.f, 0.f, 0.f);
    const int nfull = cnt >> 5;

    for (int f = 0; f < nfull; f++, base += 32) {
        uint2 r = g_slab[base + lane];
        #pragma unroll
        for (int i = 0; i < 16; i++) {
            int idx = 2 * i + half;
            unsigned sv = __shfl_sync(0xffffffffu, r.x, idx);
            float c = __uint_as_float(__shfl_sync(0xffffffffu, r.y, idx));
            float4 v = *(const float4*)(g_xT + (size_t)sv * 64 + q * 4);
            acc.x = fmaf(c, v.x, acc.x);
            acc.y = fmaf(c, v.y, acc.y);
            acc.z = fmaf(c, v.z, acc.z);
            acc.w = fmaf(c, v.w, acc.w);
        }
    }
    const int rem = end - base;
    if (rem > 0) {
        uint2 r = (lane < rem) ? g_slab[base + lane] : make_uint2(0u, 0u);
        const int npair = rem >> 1;
        for (int i = 0; i < npair; i++) {
            int idx = 2 * i + half;
            unsigned sv = __shfl_sync(0xffffffffu, r.x, idx);
            float c = __uint_as_float(__shfl_sync(0xffffffffu, r.y, idx));
            float4 v = *(const float4*)(g_xT + (size_t)sv * 64 + q * 4);
            acc.x = fmaf(c, v.x, acc.x);
            acc.y = fmaf(c, v.y, acc.y);
            acc.z = fmaf(c, v.z, acc.z);
            acc.w = fmaf(c, v.w, acc.w);
        }
        if (rem & 1) {
            unsigned sv = __shfl_sync(0xffffffffu, r.x, rem - 1);
            float c = __uint_as_float(__shfl_sync(0xffffffffu, r.y, rem - 1));
            c = (half == 0) ? c : 0.0f;
            float4 v = *(const float4*)(g_xT + (size_t)sv * 64 + q * 4);
            acc.x = fmaf(c, v.x, acc.x);
            acc.y = fmaf(c, v.y, acc.y);
            acc.z = fmaf(c, v.z, acc.z);
            acc.w = fmaf(c, v.w, acc.w);
        }
    }

    acc.x += __shfl_xor_sync(0xffffffffu, acc.x, 16);
    acc.y += __shfl_xor_sync(0xffffffffu, acc.y, 16);
    acc.z += __shfl_xor_sync(0xffffffffu, acc.z, 16);
    acc.w += __shfl_xor_sync(0xffffffffu, acc.w, 16);

    float sl = __ldg(&x[n]) * __ldg(&self_w[n]);  // x row 0
    float bs = __ldg(&bias[n]);
    if (half == 0) {
        sacc[wp][4 * q + 0] = fmaxf(fmaf(acc.x, sl, bs), 0.0f);
        sacc[wp][4 * q + 1] = fmaxf(fmaf(acc.y, sl, bs), 0.0f);
        sacc[wp][4 * q + 2] = fmaxf(fmaf(acc.z, sl, bs), 0.0f);
        sacc[wp][4 * q + 3] = fmaxf(fmaf(acc.w, sl, bs), 0.0f);
    }
    __syncthreads();

    #pragma unroll
    for (int e = threadIdx.x; e < 512; e += 256) {
        int b = e >> 3;
        int i = e & 7;
        out[(size_t)b * NN + n0 + i] = sacc[i][b];
    }
}

// ---------------------------------------------------------------------------
// Launch. Inputs: x, adj_values, w, self_w, b, src, dst.
// ---------------------------------------------------------------------------
extern "C" void kernel_launch(void* const* d_in, const int* in_sizes, int n_in,
                              void* d_out, int out_size) {
    const float* x      = (const float*)d_in[0];
    const float* adj    = (const float*)d_in[1];
    const float* w      = (const float*)d_in[2];
    const float* self_w = (const float*)d_in[3];
    const float* bias   = (const float*)d_in[4];
    const int*   src    = (const int*)d_in[5];
    const int*   dst    = (const int*)d_in[6];
    float* out = (float*)d_out;

    k_transpose<<<1250, 256>>>(x);
    k_scatter<<<EE / 4 / 256, 256>>>(adj, w, src, dst);   // 1250 blocks
    k_accum<<<NN / 8, 256>>>(x, self_w, bias, out);
}

// round 13
// speedup vs baseline: 1.9397x; 1.4522x over previous
#include <cuda_runtime.h>
#include <cuda_fp16.h>
#include <cstdint>

#define NN 20000
#define BB 64
#define EE 1280000
#define CAP 192                  // slab capacity per node (Poisson(64); 16 sigma)

// Scratch (allocation-free -> __device__ globals)
__device__ __align__(16) __half g_xTh[NN * BB];    // x transposed, fp16 [N, B]
__device__ int   g_cnt[NN];                        // zeroed in k_transpose
__device__ __align__(16) uint2 g_slab[NN * CAP];   // per-node records (src, coeff fp32)

// ---------------------------------------------------------------------------
// K0: transpose x [B,N] -> xTh [N,B] (fp16); zero g_cnt.
// LDG.128 in, conflict-free scalar LDS, STG.64 (4 halves) out.
// 1250 blocks x 256 threads; one 32n x 32b tile per block.
// ---------------------------------------------------------------------------
__global__ void __launch_bounds__(256) k_transpose(const float* __restrict__ x) {
    __shared__ float tile[32][33];
    const int n0 = (blockIdx.x >> 1) * 32;   // 625 n-tiles
    const int b0 = (blockIdx.x & 1) * 32;

    for (int i = blockIdx.x * 256 + threadIdx.x; i < NN; i += 1250 * 256)
        g_cnt[i] = 0;

    {
        const int bb = threadIdx.x >> 3;
        const int nv = (threadIdx.x & 7) * 4;
        float4 v = *(const float4*)(x + (size_t)(b0 + bb) * NN + n0 + nv);
        tile[nv + 0][bb] = v.x;
        tile[nv + 1][bb] = v.y;
        tile[nv + 2][bb] = v.z;
        tile[nv + 3][bb] = v.w;
    }
    __syncthreads();
    {
        const int nl = threadIdx.x >> 3;
        const int bv = (threadIdx.x & 7) * 4;
        __half2 h01 = __floats2half2_rn(tile[nl][bv + 0], tile[nl][bv + 1]);
        __half2 h23 = __floats2half2_rn(tile[nl][bv + 2], tile[nl][bv + 3]);
        uint2 u;
        u.x = *reinterpret_cast<unsigned*>(&h01);
        u.y = *reinterpret_cast<unsigned*>(&h23);
        // byte offset = 2*(n*64 + b0+bv), bv%4==0 -> 8B aligned
        *reinterpret_cast<uint2*>(g_xTh + (size_t)(n0 + nl) * 64 + b0 + bv) = u;
    }
}

// ---------------------------------------------------------------------------
// K1: direct slab scatter (R8-proven). 4 edges/thread, vectorized loads.
// ---------------------------------------------------------------------------
__global__ void k_scatter(const float* __restrict__ adj,
                          const float* __restrict__ w,
                          const int* __restrict__ src,
                          const int* __restrict__ dst) {
    int t = blockIdx.x * 256 + threadIdx.x;      // < 320000 (EE/4)
    int4   s = __ldg(&((const int4*)src)[t]);
    int4   d = __ldg(&((const int4*)dst)[t]);
    float4 a = __ldg(&((const float4*)adj)[t]);
    float4 q = __ldg(&((const float4*)w)[t]);

    int p0 = atomicAdd(&g_cnt[d.x], 1);
    int p1 = atomicAdd(&g_cnt[d.y], 1);
    int p2 = atomicAdd(&g_cnt[d.z], 1);
    int p3 = atomicAdd(&g_cnt[d.w], 1);

    if (p0 < CAP) g_slab[(size_t)d.x * CAP + p0] =
        make_uint2((unsigned)s.x, __float_as_uint(a.x * q.x));
    if (p1 < CAP) g_slab[(size_t)d.y * CAP + p1] =
        make_uint2((unsigned)s.y, __float_as_uint(a.y * q.y));
    if (p2 < CAP) g_slab[(size_t)d.z * CAP + p2] =
        make_uint2((unsigned)s.z, __float_as_uint(a.z * q.z));
    if (p3 < CAP) g_slab[(size_t)d.w * CAP + p3] =
        make_uint2((unsigned)s.w, __float_as_uint(a.w * q.w));
}

// ---------------------------------------------------------------------------
// K2: warp-per-node accumulation + fused epilogue, fp16 gathers.
// Quarter-warp scheme: lane = q4*8 + f8. Quarter q4 handles record 4i+q4;
// lane owns features [8*f8, 8*f8+8) as one LDG.128 of 8 halves. Accumulate
// fp32; reduce across quarters with shfl_xor(8), shfl_xor(16).
// ---------------------------------------------------------------------------
__global__ void __launch_bounds__(256) k_accum(const float* __restrict__ x,
                                               const float* __restrict__ self_w,
                                               const float* __restrict__ bias,
                                               float* __restrict__ out) {
    __shared__ float sacc[8][65];
    const int wp = threadIdx.x >> 5;
    const int lane = threadIdx.x & 31;
    const int q4 = lane >> 3;          // 0..3
    const int f8 = lane & 7;           // feature octet
    const int n0 = blockIdx.x * 8;
    const int n = n0 + wp;

    const int cnt = min(__ldg(&g_cnt[n]), CAP);
    int base = n * CAP;

    float acc0 = 0.f, acc1 = 0.f, acc2 = 0.f, acc3 = 0.f;
    float acc4 = 0.f, acc5 = 0.f, acc6 = 0.f, acc7 = 0.f;
    const int nfull = cnt >> 5;

    for (int f = 0; f < nfull; f++, base += 32) {
        uint2 r = g_slab[base + lane];
        #pragma unroll
        for (int i = 0; i < 8; i++) {
            int idx = 4 * i + q4;
            unsigned sv = __shfl_sync(0xffffffffu, r.x, idx);
            float c = __uint_as_float(__shfl_sync(0xffffffffu, r.y, idx));
            uint4 hv = *(const uint4*)(g_xTh + (size_t)sv * 64 + f8 * 8);
            float2 f0 = __half22float2(*reinterpret_cast<__half2*>(&hv.x));
            float2 f1 = __half22float2(*reinterpret_cast<__half2*>(&hv.y));
            float2 f2 = __half22float2(*reinterpret_cast<__half2*>(&hv.z));
            float2 f3 = __half22float2(*reinterpret_cast<__half2*>(&hv.w));
            acc0 = fmaf(c, f0.x, acc0); acc1 = fmaf(c, f0.y, acc1);
            acc2 = fmaf(c, f1.x, acc2); acc3 = fmaf(c, f1.y, acc3);
            acc4 = fmaf(c, f2.x, acc4); acc5 = fmaf(c, f2.y, acc5);
            acc6 = fmaf(c, f3.x, acc6); acc7 = fmaf(c, f3.y, acc7);
        }
    }
    const int rem = cnt & 31;
    if (rem > 0) {
        uint2 r = (lane < rem) ? g_slab[base + lane] : make_uint2(0u, 0u);
        const int nquad = (rem + 3) >> 2;
        for (int i = 0; i < nquad; i++) {
            int idx = 4 * i + q4;
            unsigned sv = __shfl_sync(0xffffffffu, r.x, idx);
            float c = __uint_as_float(__shfl_sync(0xffffffffu, r.y, idx));
            c = (idx < rem) ? c : 0.0f;      // padded lanes carry sv=0, c=0
            uint4 hv = *(const uint4*)(g_xTh + (size_t)sv * 64 + f8 * 8);
            float2 f0 = __half22float2(*reinterpret_cast<__half2*>(&hv.x));
            float2 f1 = __half22float2(*reinterpret_cast<__half2*>(&hv.y));
            float2 f2 = __half22float2(*reinterpret_cast<__half2*>(&hv.z));
            float2 f3 = __half22float2(*reinterpret_cast<__half2*>(&hv.w));
            acc0 = fmaf(c, f0.x, acc0); acc1 = fmaf(c, f0.y, acc1);
            acc2 = fmaf(c, f1.x, acc2); acc3 = fmaf(c, f1.y, acc3);
            acc4 = fmaf(c, f2.x, acc4); acc5 = fmaf(c, f2.y, acc5);
            acc6 = fmaf(c, f3.x, acc6); acc7 = fmaf(c, f3.y, acc7);
        }
    }

    // Reduce the 4 quarter-warp partial sums (lanes differ only in q4).
    #pragma unroll
    for (int m = 8; m <= 16; m <<= 1) {
        acc0 += __shfl_xor_sync(0xffffffffu, acc0, m);
        acc1 += __shfl_xor_sync(0xffffffffu, acc1, m);
        acc2 += __shfl_xor_sync(0xffffffffu, acc2, m);
        acc3 += __shfl_xor_sync(0xffffffffu, acc3, m);
        acc4 += __shfl_xor_sync(0xffffffffu, acc4, m);
        acc5 += __shfl_xor_sync(0xffffffffu, acc5, m);
        acc6 += __shfl_xor_sync(0xffffffffu, acc6, m);
        acc7 += __shfl_xor_sync(0xffffffffu, acc7, m);
    }

    float sl = __ldg(&x[n]) * __ldg(&self_w[n]);  // x row 0
    float bs = __ldg(&bias[n]);
    if (q4 == 0) {
        float* sp = &sacc[wp][8 * f8];
        sp[0] = fmaxf(fmaf(acc0, sl, bs), 0.0f);
        sp[1] = fmaxf(fmaf(acc1, sl, bs), 0.0f);
        sp[2] = fmaxf(fmaf(acc2, sl, bs), 0.0f);
        sp[3] = fmaxf(fmaf(acc3, sl, bs), 0.0f);
        sp[4] = fmaxf(fmaf(acc4, sl, bs), 0.0f);
        sp[5] = fmaxf(fmaf(acc5, sl, bs), 0.0f);
        sp[6] = fmaxf(fmaf(acc6, sl, bs), 0.0f);
        sp[7] = fmaxf(fmaf(acc7, sl, bs), 0.0f);
    }
    __syncthreads();

    #pragma unroll
    for (int e = threadIdx.x; e < 512; e += 256) {
        int b = e >> 3;
        int i = e & 7;
        out[(size_t)b * NN + n0 + i] = sacc[i][b];
    }
}

// ---------------------------------------------------------------------------
// Launch. Inputs: x, adj_values, w, self_w, b, src, dst.
// ---------------------------------------------------------------------------
extern "C" void kernel_launch(void* const* d_in, const int* in_sizes, int n_in,
                              void* d_out, int out_size) {
    const float* x      = (const float*)d_in[0];
    const float* adj    = (const float*)d_in[1];
    const float* w      = (const float*)d_in[2];
    const float* self_w = (const float*)d_in[3];
    const float* bias   = (const float*)d_in[4];
    const int*   src    = (const int*)d_in[5];
    const int*   dst    = (const int*)d_in[6];
    float* out = (float*)d_out;

    k_transpose<<<1250, 256>>>(x);
    k_scatter<<<EE / 4 / 256, 256>>>(adj, w, src, dst);   // 1250 blocks
    k_accum<<<NN / 8, 256>>>(x, self_w, bias, out);
}

// round 15
// speedup vs baseline: 2.0336x; 1.0484x over previous
#include <cuda_runtime.h>
#include <cuda_fp16.h>
#include <cstdint>

#define NN 20000
#define BB 64
#define EE 1280000
#define CAP 192                  // slab capacity per node (Poisson(64); 16 sigma)

// Scratch (allocation-free -> __device__ globals)
__device__ __align__(16) __half g_xTh[NN * BB];      // x transposed, fp16 [N, B]
__device__ int g_cnt[NN];                            // zeroed in k_transpose
__device__ __align__(16) unsigned g_slab[NN * CAP];  // packed (src<<16 | fp16 coeff)

// ---------------------------------------------------------------------------
// K0: transpose x [B,N] -> xTh [N,B] (fp16); zero g_cnt. (R13-proven)
// ---------------------------------------------------------------------------
__global__ void __launch_bounds__(256) k_transpose(const float* __restrict__ x) {
    __shared__ float tile[32][33];
    const int n0 = (blockIdx.x >> 1) * 32;   // 625 n-tiles
    const int b0 = (blockIdx.x & 1) * 32;

    for (int i = blockIdx.x * 256 + threadIdx.x; i < NN; i += 1250 * 256)
        g_cnt[i] = 0;

    {
        const int bb = threadIdx.x >> 3;
        const int nv = (threadIdx.x & 7) * 4;
        float4 v = *(const float4*)(x + (size_t)(b0 + bb) * NN + n0 + nv);
        tile[nv + 0][bb] = v.x;
        tile[nv + 1][bb] = v.y;
        tile[nv + 2][bb] = v.z;
        tile[nv + 3][bb] = v.w;
    }
    __syncthreads();
    {
        const int nl = threadIdx.x >> 3;
        const int bv = (threadIdx.x & 7) * 4;
        __half2 h01 = __floats2half2_rn(tile[nl][bv + 0], tile[nl][bv + 1]);
        __half2 h23 = __floats2half2_rn(tile[nl][bv + 2], tile[nl][bv + 3]);
        uint2 u;
        u.x = *reinterpret_cast<unsigned*>(&h01);
        u.y = *reinterpret_cast<unsigned*>(&h23);
        *reinterpret_cast<uint2*>(g_xTh + (size_t)(n0 + nl) * 64 + b0 + bv) = u;
    }
}

// ---------------------------------------------------------------------------
// K1: slab scatter, 8 edges/thread (MLP 8 on the atomic chains), packed
// 4-byte records. 625 blocks x 256 threads.
// ---------------------------------------------------------------------------
__device__ __forceinline__ unsigned pack_rec(int s, float c) {
    return ((unsigned)s << 16) | (unsigned)__half_as_ushort(__float2half_rn(c));
}

__global__ void k_scatter(const float* __restrict__ adj,
                          const float* __restrict__ w,
                          const int* __restrict__ src,
                          const int* __restrict__ dst) {
    int t = blockIdx.x * 256 + threadIdx.x;      // < 160000 (EE/8)
    int4   s0 = __ldg(&((const int4*)src)[2 * t]);
    int4   s1 = __ldg(&((const int4*)src)[2 * t + 1]);
    int4   d0 = __ldg(&((const int4*)dst)[2 * t]);
    int4   d1 = __ldg(&((const int4*)dst)[2 * t + 1]);
    float4 a0 = __ldg(&((const float4*)adj)[2 * t]);
    float4 a1 = __ldg(&((const float4*)adj)[2 * t + 1]);
    float4 q0 = __ldg(&((const float4*)w)[2 * t]);
    float4 q1 = __ldg(&((const float4*)w)[2 * t + 1]);

    int p0 = atomicAdd(&g_cnt[d0.x], 1);
    int p1 = atomicAdd(&g_cnt[d0.y], 1);
    int p2 = atomicAdd(&g_cnt[d0.z], 1);
    int p3 = atomicAdd(&g_cnt[d0.w], 1);
    int p4 = atomicAdd(&g_cnt[d1.x], 1);
    int p5 = atomicAdd(&g_cnt[d1.y], 1);
    int p6 = atomicAdd(&g_cnt[d1.z], 1);
    int p7 = atomicAdd(&g_cnt[d1.w], 1);

    if (p0 < CAP) g_slab[(size_t)d0.x * CAP + p0] = pack_rec(s0.x, a0.x * q0.x);
    if (p1 < CAP) g_slab[(size_t)d0.y * CAP + p1] = pack_rec(s0.y, a0.y * q0.y);
    if (p2 < CAP) g_slab[(size_t)d0.z * CAP + p2] = pack_rec(s0.z, a0.z * q0.z);
    if (p3 < CAP) g_slab[(size_t)d0.w * CAP + p3] = pack_rec(s0.w, a0.w * q0.w);
    if (p4 < CAP) g_slab[(size_t)d1.x * CAP + p4] = pack_rec(s1.x, a1.x * q1.x);
    if (p5 < CAP) g_slab[(size_t)d1.y * CAP + p5] = pack_rec(s1.y, a1.y * q1.y);
    if (p6 < CAP) g_slab[(size_t)d1.z * CAP + p6] = pack_rec(s1.z, a1.z * q1.z);
    if (p7 < CAP) g_slab[(size_t)d1.w * CAP + p7] = pack_rec(s1.w, a1.w * q1.w);
}

// ---------------------------------------------------------------------------
// K2: warp-per-node accumulation + fused epilogue, fp16 gathers, packed
// records (1 SHFL per record). Quarter-warp scheme: lane = q4*8 + f8;
// quarter q4 handles record 4i+q4; lane owns 8 features (one LDG.128).
// ---------------------------------------------------------------------------
__global__ void __launch_bounds__(256) k_accum(const float* __restrict__ x,
                                               const float* __restrict__ self_w,
                                               const float* __restrict__ bias,
                                               float* __restrict__ out) {
    __shared__ float sacc[8][65];
    const int wp = threadIdx.x >> 5;
    const int lane = threadIdx.x & 31;
    const int q4 = lane >> 3;          // 0..3
    const int f8 = lane & 7;           // feature octet
    const int n0 = blockIdx.x * 8;
    const int n = n0 + wp;

    const int cnt = min(__ldg(&g_cnt[n]), CAP);
    int base = n * CAP;

    float acc0 = 0.f, acc1 = 0.f, acc2 = 0.f, acc3 = 0.f;
    float acc4 = 0.f, acc5 = 0.f, acc6 = 0.f, acc7 = 0.f;
    const int nfull = cnt >> 5;

    for (int f = 0; f < nfull; f++, base += 32) {
        unsigned r = g_slab[base + lane];
        #pragma unroll
        for (int i = 0; i < 8; i++) {
            unsigned rec = __shfl_sync(0xffffffffu, r, 4 * i + q4);
            unsigned sv = rec >> 16;
            float c = __half2float(__ushort_as_half((unsigned short)(rec & 0xffffu)));
            uint4 hv = *(const uint4*)(g_xTh + (size_t)sv * 64 + f8 * 8);
            float2 f0 = __half22float2(*reinterpret_cast<__half2*>(&hv.x));
            float2 f1 = __half22float2(*reinterpret_cast<__half2*>(&hv.y));
            float2 f2 = __half22float2(*reinterpret_cast<__half2*>(&hv.z));
            float2 f3 = __half22float2(*reinterpret_cast<__half2*>(&hv.w));
            acc0 = fmaf(c, f0.x, acc0); acc1 = fmaf(c, f0.y, acc1);
            acc2 = fmaf(c, f1.x, acc2); acc3 = fmaf(c, f1.y, acc3);
            acc4 = fmaf(c, f2.x, acc4); acc5 = fmaf(c, f2.y, acc5);
            acc6 = fmaf(c, f3.x, acc6); acc7 = fmaf(c, f3.y, acc7);
        }
    }
    const int rem = cnt & 31;
    if (rem > 0) {
        unsigned r = (lane < rem) ? g_slab[base + lane] : 0u;  // rec 0: src 0, coeff +0
        const int nquad = (rem + 3) >> 2;
        for (int i = 0; i < nquad; i++) {
            int idx = 4 * i + q4;
            unsigned rec = __shfl_sync(0xffffffffu, r, idx);
            unsigned sv = rec >> 16;
            float c = __half2float(__ushort_as_half((unsigned short)(rec & 0xffffu)));
            c = (idx < rem) ? c : 0.0f;
            uint4 hv = *(const uint4*)(g_xTh + (size_t)sv * 64 + f8 * 8);
            float2 f0 = __half22float2(*reinterpret_cast<__half2*>(&hv.x));
            float2 f1 = __half22float2(*reinterpret_cast<__half2*>(&hv.y));
            float2 f2 = __half22float2(*reinterpret_cast<__half2*>(&hv.z));
            float2 f3 = __half22float2(*reinterpret_cast<__half2*>(&hv.w));
            acc0 = fmaf(c, f0.x, acc0); acc1 = fmaf(c, f0.y, acc1);
            acc2 = fmaf(c, f1.x, acc2); acc3 = fmaf(c, f1.y, acc3);
            acc4 = fmaf(c, f2.x, acc4); acc5 = fmaf(c, f2.y, acc5);
            acc6 = fmaf(c, f3.x, acc6); acc7 = fmaf(c, f3.y, acc7);
        }
    }

    // Reduce the 4 quarter-warp partials (lanes differ only in q4).
    #pragma unroll
    for (int m = 8; m <= 16; m <<= 1) {
        acc0 += __shfl_xor_sync(0xffffffffu, acc0, m);
        acc1 += __shfl_xor_sync(0xffffffffu, acc1, m);
        acc2 += __shfl_xor_sync(0xffffffffu, acc2, m);
        acc3 += __shfl_xor_sync(0xffffffffu, acc3, m);
        acc4 += __shfl_xor_sync(0xffffffffu, acc4, m);
        acc5 += __shfl_xor_sync(0xffffffffu, acc5, m);
        acc6 += __shfl_xor_sync(0xffffffffu, acc6, m);
        acc7 += __shfl_xor_sync(0xffffffffu, acc7, m);
    }

    float sl = __ldg(&x[n]) * __ldg(&self_w[n]);  // x row 0
    float bs = __ldg(&bias[n]);
    if (q4 == 0) {
        float* sp = &sacc[wp][8 * f8];
        sp[0] = fmaxf(fmaf(acc0, sl, bs), 0.0f);
        sp[1] = fmaxf(fmaf(acc1, sl, bs), 0.0f);
        sp[2] = fmaxf(fmaf(acc2, sl, bs), 0.0f);
        sp[3] = fmaxf(fmaf(acc3, sl, bs), 0.0f);
        sp[4] = fmaxf(fmaf(acc4, sl, bs), 0.0f);
        sp[5] = fmaxf(fmaf(acc5, sl, bs), 0.0f);
        sp[6] = fmaxf(fmaf(acc6, sl, bs), 0.0f);
        sp[7] = fmaxf(fmaf(acc7, sl, bs), 0.0f);
    }
    __syncthreads();

    #pragma unroll
    for (int e = threadIdx.x; e < 512; e += 256) {
        int b = e >> 3;
        int i = e & 7;
        out[(size_t)b * NN + n0 + i] = sacc[i][b];
    }
}

// ---------------------------------------------------------------------------
// Launch. Inputs: x, adj_values, w, self_w, b, src, dst.
// ---------------------------------------------------------------------------
extern "C" void kernel_launch(void* const* d_in, const int* in_sizes, int n_in,
                              void* d_out, int out_size) {
    const float* x      = (const float*)d_in[0];
    const float* adj    = (const float*)d_in[1];
    const float* w      = (const float*)d_in[2];
    const float* self_w = (const float*)d_in[3];
    const float* bias   = (const float*)d_in[4];
    const int*   src    = (const int*)d_in[5];
    const int*   dst    = (const int*)d_in[6];
    float* out = (float*)d_out;

    k_transpose<<<1250, 256>>>(x);
    k_scatter<<<EE / 8 / 256, 256>>>(adj, w, src, dst);   // 625 blocks
    k_accum<<<NN / 8, 256>>>(x, self_w, bias, out);
}